// round 11
// baseline (speedup 1.0000x reference)
#include <cuda_runtime.h>

// Fixed problem constants:
//   x: (4,1,128,2048) f32 ; vals: 16.7M f32 ; rows/cols: 16.7M int32-or-int64 (rows sorted)
//   out: (4,1,512,256) f32 = 524288 elements
#define NNZ_TOTAL   16777216
#define NCOLS       262144      // NS*NC = 2048*128
#define OUT_PLANE   131072      // per-bk output plane (Nz*Nx)
#define TOTAL_WARPS 8192
#define NNZ_PER_WARP (NNZ_TOTAL / TOTAL_WARPS)   // 2048
#define ITERS        (NNZ_PER_WARP / 32)         // 64

// Scratch: transposed RHS, rhs_t[col] = {x[0,c,s], x[1,c,s], x[2,c,s], x[3,c,s]}, col = s*128 + c
static __device__ float4  g_rhs[NCOLS];          // 4 MB, L2-resident during main kernel
static __device__ unsigned g_stride;             // 2 if indices are int64, 1 if int32

// --- fused prep (vectorized, bounds-checked): probe + zero out + build rhs -----
// 131072 threads. Every thread zeroes one float4 of out (covers all 524288
// floats). Threads gid<65536 additionally build 4 rhs entries:
//   s4 = gid>>7 in [0,512), c = gid&127 in [0,128)
//   o4 = c*512 + s4  -> x4[o4 + p*65536] = x[p, c, 4*s4 .. 4*s4+3]   (p = bk)
//   col_j = (4*s4+j)*128 + c = s4*512 + j*128 + c  -> coalesced g_rhs stores
// Max indices: x4: 127*512+511 + 3*65536 = 262143 < 262144 OK
//              g_rhs: 511*512+127+384 = 262143 < 262144 OK
// dtype probe: word [NNZ-1] (u32 view) is in-bounds for both layouts:
//   int64: HIGH half of element (NNZ-2)/2 -> always 0 ; int32: last sorted row != 0
__global__ void k_prep(const float4* __restrict__ x4,
                       const unsigned* __restrict__ rows_u32,
                       float4* __restrict__ out4) {
    unsigned gid = blockIdx.x * blockDim.x + threadIdx.x;   // < 131072
    if (gid == 0) g_stride = (rows_u32[NNZ_TOTAL - 1] == 0u) ? 2u : 1u;
    out4[gid] = make_float4(0.f, 0.f, 0.f, 0.f);            // d_out poisoned 0xAA
    if (gid < 65536u) {
        unsigned s4 = gid >> 7;               // [0,512)
        unsigned c  = gid & 127u;             // [0,128)
        unsigned o4 = c * 512u + s4;          // float4 idx in plane (c*2048+4*s4)/4
        float4 b0 = x4[o4];                   // x[0, c, 4*s4 .. 4*s4+3]
        float4 b1 = x4[o4 + 65536u];          // x[1, ...]
        float4 b2 = x4[o4 + 131072u];         // x[2, ...]
        float4 b3 = x4[o4 + 196608u];         // x[3, ...]
        unsigned col = s4 * 512u + c;
        g_rhs[col]        = make_float4(b0.x, b1.x, b2.x, b3.x);
        g_rhs[col + 128u] = make_float4(b0.y, b1.y, b2.y, b3.y);
        g_rhs[col + 256u] = make_float4(b0.z, b1.z, b2.z, b3.z);
        g_rhs[col + 384u] = make_float4(b0.w, b1.w, b2.w, b3.w);
    }
}

// --- flush one completed row: butterfly reduce + 4 atomics (cold path) ---------
__device__ __forceinline__ void flush_row(unsigned row,
                                          float a0, float a1, float a2, float a3,
                                          unsigned lane,
                                          float* __restrict__ out) {
    #pragma unroll
    for (int d = 16; d > 0; d >>= 1) {
        a0 += __shfl_xor_sync(0xffffffffu, a0, d);
        a1 += __shfl_xor_sync(0xffffffffu, a1, d);
        a2 += __shfl_xor_sync(0xffffffffu, a2, d);
        a3 += __shfl_xor_sync(0xffffffffu, a3, d);
    }
    if (lane < 4u) {
        float s = (lane == 0u) ? a0 : (lane == 1u) ? a1 : (lane == 2u) ? a2 : a3;
        // out layout: bk*131072 + z*256 + x, with row r = x*512 + z
        unsigned o = (row & 511u) * 256u + (row >> 9);
        atomicAdd(out + lane * OUT_PLANE + o, s);
    }
}

// --- main SpMM: byte-identical to the proven best (78.0us, 32 regs, occ ~82%) --
// Depth-1 software pipeline; empirical optimum across 8 structural variants.
// L1-busy is pinned at the 16.7M gather-wavefront floor (~60us); L2 at ~58us.
__global__ void __launch_bounds__(256)
k_spmm(const float* __restrict__ vals,
       const unsigned* __restrict__ rows_u32,
       const unsigned* __restrict__ cols_u32,
       float* __restrict__ out) {
    const unsigned warp_id = (blockIdx.x * blockDim.x + threadIdx.x) >> 5;
    const unsigned lane    = threadIdx.x & 31u;
    const unsigned st      = g_stride;          // 1 (int32) or 2 (int64, read low word)
    const unsigned base    = warp_id * NNZ_PER_WARP;
    const unsigned rstep   = st * 32u;

    const float*    vp = vals     + base + lane;
    const unsigned* rp = rows_u32 + st * (base + lane);
    const unsigned* cp = cols_u32 + st * (base + lane);

    // pipeline stage 0
    float    v   = *vp;
    unsigned row = *rp;
    unsigned col = *cp;
    float4   r   = g_rhs[col];

    unsigned cur_row = __shfl_sync(0xffffffffu, row, 0);
    float a0 = 0.f, a1 = 0.f, a2 = 0.f, a3 = 0.f;

    #pragma unroll 1
    for (int it = 0; it < ITERS - 1; ++it) {
        // prefetch next iteration (hides gather latency behind the logic below)
        vp += 32u; rp += rstep; cp += rstep;
        float    vn   = *vp;
        unsigned rown = *rp;
        unsigned coln = *cp;
        float4   rn   = g_rhs[coln];

        float c0 = v * r.x, c1 = v * r.y, c2 = v * r.z, c3 = v * r.w;
        if (__all_sync(0xffffffffu, row == cur_row)) {       // fast path (~75%)
            a0 += c0; a1 += c1; a2 += c2; a3 += c3;
        } else {                                             // row boundary in group
            unsigned r31 = __shfl_sync(0xffffffffu, row, 31);
            bool mine = (row == cur_row);                    // sorted -> prefix lanes
            if (mine) { a0 += c0; a1 += c1; a2 += c2; a3 += c3; }
            flush_row(cur_row, a0, a1, a2, a3, lane, out);
            if (!mine && row != r31) {
                // row fully contained inside this group (needs <32 nnz): direct atomics
                unsigned o = (row & 511u) * 256u + (row >> 9);
                atomicAdd(out + o,                  c0);
                atomicAdd(out + OUT_PLANE + o,      c1);
                atomicAdd(out + 2u * OUT_PLANE + o, c2);
                atomicAdd(out + 3u * OUT_PLANE + o, c3);
            }
            bool last = (row == r31);                        // suffix lanes: new row
            a0 = last ? c0 : 0.f;
            a1 = last ? c1 : 0.f;
            a2 = last ? c2 : 0.f;
            a3 = last ? c3 : 0.f;
            cur_row = r31;
        }
        v = vn; row = rown; r = rn;
    }

    // epilogue: process final group
    {
        float c0 = v * r.x, c1 = v * r.y, c2 = v * r.z, c3 = v * r.w;
        if (__all_sync(0xffffffffu, row == cur_row)) {
            a0 += c0; a1 += c1; a2 += c2; a3 += c3;
        } else {
            unsigned r31 = __shfl_sync(0xffffffffu, row, 31);
            bool mine = (row == cur_row);
            if (mine) { a0 += c0; a1 += c1; a2 += c2; a3 += c3; }
            flush_row(cur_row, a0, a1, a2, a3, lane, out);
            if (!mine && row != r31) {
                unsigned o = (row & 511u) * 256u + (row >> 9);
                atomicAdd(out + o,                  c0);
                atomicAdd(out + OUT_PLANE + o,      c1);
                atomicAdd(out + 2u * OUT_PLANE + o, c2);
                atomicAdd(out + 3u * OUT_PLANE + o, c3);
            }
            bool last = (row == r31);
            a0 = last ? c0 : 0.f;
            a1 = last ? c1 : 0.f;
            a2 = last ? c2 : 0.f;
            a3 = last ? c3 : 0.f;
            cur_row = r31;
        }
    }
    flush_row(cur_row, a0, a1, a2, a3, lane, out);
}

extern "C" void kernel_launch(void* const* d_in, const int* in_sizes, int n_in,
                              void* d_out, int out_size) {
    const float*    x    = (const float*)d_in[0];
    const float*    vals = (const float*)d_in[1];
    const unsigned* rows = (const unsigned*)d_in[2];
    const unsigned* cols = (const unsigned*)d_in[3];
    float*          out  = (float*)d_out;

    k_prep<<<131072 / 256, 256>>>((const float4*)x, rows, (float4*)out);
    k_spmm<<<TOTAL_WARPS * 32 / 256, 256>>>(vals, rows, cols, out);
}

// round 12
// speedup vs baseline: 1.0496x; 1.0496x over previous
#include <cuda_runtime.h>

// Fixed problem constants:
//   x: (4,1,128,2048) f32 ; vals: 16.7M f32 ; rows/cols: 16.7M int32-or-int64 (rows sorted)
//   out: (4,1,512,256) f32 = 524288 elements
#define NNZ_TOTAL   16777216
#define NCOLS       262144      // NS*NC = 2048*128
#define OUT_PLANE   131072      // per-bk output plane (Nz*Nx)
#define TOTAL_WARPS 8192
#define NNZ_PER_WARP (NNZ_TOTAL / TOTAL_WARPS)   // 2048
#define ITERS        (NNZ_PER_WARP / 32)         // 64

// Scratch: transposed RHS, rhs_t[col] = {x[0,c,s], x[1,c,s], x[2,c,s], x[3,c,s]}, col = s*128 + c
static __device__ float4  g_rhs[NCOLS];          // 4 MB, L2-resident during main kernel
static __device__ unsigned g_stride;             // 2 if indices are int64, 1 if int32

// --- fused prep (vectorized, bounds-checked): probe + zero out + build rhs -----
// 131072 threads. Every thread zeroes one float4 of out (covers all 524288
// floats). Threads gid<65536 additionally build 4 rhs entries:
//   s4 = gid>>7 in [0,512), c = gid&127 in [0,128)
//   o4 = c*512 + s4  -> x4[o4 + p*65536] = x[p, c, 4*s4 .. 4*s4+3]   (p = bk)
//   col_j = (4*s4+j)*128 + c = s4*512 + j*128 + c  -> coalesced g_rhs stores
// Max indices: x4: 127*512+511 + 3*65536 = 262143 < 262144 OK
//              g_rhs: 511*512+127+384 = 262143 < 262144 OK
// dtype probe: word [NNZ-1] (u32 view) is in-bounds for both layouts:
//   int64: HIGH half of element (NNZ-2)/2 -> always 0 ; int32: last sorted row != 0
__global__ void k_prep(const float4* __restrict__ x4,
                       const unsigned* __restrict__ rows_u32,
                       float4* __restrict__ out4) {
    unsigned gid = blockIdx.x * blockDim.x + threadIdx.x;   // < 131072
    if (gid == 0) g_stride = (rows_u32[NNZ_TOTAL - 1] == 0u) ? 2u : 1u;
    out4[gid] = make_float4(0.f, 0.f, 0.f, 0.f);            // d_out poisoned 0xAA
    if (gid < 65536u) {
        unsigned s4 = gid >> 7;               // [0,512)
        unsigned c  = gid & 127u;             // [0,128)
        unsigned o4 = c * 512u + s4;          // float4 idx in plane (c*2048+4*s4)/4
        float4 b0 = x4[o4];                   // x[0, c, 4*s4 .. 4*s4+3]
        float4 b1 = x4[o4 + 65536u];          // x[1, ...]
        float4 b2 = x4[o4 + 131072u];         // x[2, ...]
        float4 b3 = x4[o4 + 196608u];         // x[3, ...]
        unsigned col = s4 * 512u + c;
        g_rhs[col]        = make_float4(b0.x, b1.x, b2.x, b3.x);
        g_rhs[col + 128u] = make_float4(b0.y, b1.y, b2.y, b3.y);
        g_rhs[col + 256u] = make_float4(b0.z, b1.z, b2.z, b3.z);
        g_rhs[col + 384u] = make_float4(b0.w, b1.w, b2.w, b3.w);
    }
}

// --- flush one completed row: butterfly reduce + 4 atomics (cold path) ---------
__device__ __forceinline__ void flush_row(unsigned row,
                                          float a0, float a1, float a2, float a3,
                                          unsigned lane,
                                          float* __restrict__ out) {
    #pragma unroll
    for (int d = 16; d > 0; d >>= 1) {
        a0 += __shfl_xor_sync(0xffffffffu, a0, d);
        a1 += __shfl_xor_sync(0xffffffffu, a1, d);
        a2 += __shfl_xor_sync(0xffffffffu, a2, d);
        a3 += __shfl_xor_sync(0xffffffffu, a3, d);
    }
    if (lane < 4u) {
        float s = (lane == 0u) ? a0 : (lane == 1u) ? a1 : (lane == 2u) ? a2 : a3;
        // out layout: bk*131072 + z*256 + x, with row r = x*512 + z
        unsigned o = (row & 511u) * 256u + (row >> 9);
        atomicAdd(out + lane * OUT_PLANE + o, s);
    }
}

// --- main SpMM: proven best shape (77-78us, 32 regs, occ ~82%) ------------------
// Depth-1 software pipeline; empirical optimum across 9 structural variants.
// L1tex wavefront floor (~37 wf / warp-iter) puts the limit at ~68us; this
// schedule achieves ~87% of it. Payload shrinking can't help (1 line + 1
// sector per gather regardless of size <=16B).
__global__ void __launch_bounds__(256)
k_spmm(const float* __restrict__ vals,
       const unsigned* __restrict__ rows_u32,
       const unsigned* __restrict__ cols_u32,
       float* __restrict__ out) {
    const unsigned warp_id = (blockIdx.x * blockDim.x + threadIdx.x) >> 5;
    const unsigned lane    = threadIdx.x & 31u;
    const unsigned st      = g_stride;          // 1 (int32) or 2 (int64, read low word)
    const unsigned base    = warp_id * NNZ_PER_WARP;
    const unsigned rstep   = st * 32u;

    const float*    vp = vals     + base + lane;
    const unsigned* rp = rows_u32 + st * (base + lane);
    const unsigned* cp = cols_u32 + st * (base + lane);

    // pipeline stage 0
    float    v   = *vp;
    unsigned row = *rp;
    unsigned col = *cp;
    float4   r   = g_rhs[col];

    unsigned cur_row = __shfl_sync(0xffffffffu, row, 0);
    float a0 = 0.f, a1 = 0.f, a2 = 0.f, a3 = 0.f;

    #pragma unroll 1
    for (int it = 0; it < ITERS - 1; ++it) {
        // prefetch next iteration (hides gather latency behind the logic below)
        vp += 32u; rp += rstep; cp += rstep;
        float    vn   = *vp;
        unsigned rown = *rp;
        unsigned coln = *cp;
        float4   rn   = g_rhs[coln];

        float c0 = v * r.x, c1 = v * r.y, c2 = v * r.z, c3 = v * r.w;
        if (__all_sync(0xffffffffu, row == cur_row)) {       // fast path (~75%)
            a0 += c0; a1 += c1; a2 += c2; a3 += c3;
        } else {                                             // row boundary in group
            unsigned r31 = __shfl_sync(0xffffffffu, row, 31);
            bool mine = (row == cur_row);                    // sorted -> prefix lanes
            if (mine) { a0 += c0; a1 += c1; a2 += c2; a3 += c3; }
            flush_row(cur_row, a0, a1, a2, a3, lane, out);
            if (!mine && row != r31) {
                // row fully contained inside this group (needs <32 nnz): direct atomics
                unsigned o = (row & 511u) * 256u + (row >> 9);
                atomicAdd(out + o,                  c0);
                atomicAdd(out + OUT_PLANE + o,      c1);
                atomicAdd(out + 2u * OUT_PLANE + o, c2);
                atomicAdd(out + 3u * OUT_PLANE + o, c3);
            }
            bool last = (row == r31);                        // suffix lanes: new row
            a0 = last ? c0 : 0.f;
            a1 = last ? c1 : 0.f;
            a2 = last ? c2 : 0.f;
            a3 = last ? c3 : 0.f;
            cur_row = r31;
        }
        v = vn; row = rown; r = rn;
    }

    // epilogue: process final group
    {
        float c0 = v * r.x, c1 = v * r.y, c2 = v * r.z, c3 = v * r.w;
        if (__all_sync(0xffffffffu, row == cur_row)) {
            a0 += c0; a1 += c1; a2 += c2; a3 += c3;
        } else {
            unsigned r31 = __shfl_sync(0xffffffffu, row, 31);
            bool mine = (row == cur_row);
            if (mine) { a0 += c0; a1 += c1; a2 += c2; a3 += c3; }
            flush_row(cur_row, a0, a1, a2, a3, lane, out);
            if (!mine && row != r31) {
                unsigned o = (row & 511u) * 256u + (row >> 9);
                atomicAdd(out + o,                  c0);
                atomicAdd(out + OUT_PLANE + o,      c1);
                atomicAdd(out + 2u * OUT_PLANE + o, c2);
                atomicAdd(out + 3u * OUT_PLANE + o, c3);
            }
            bool last = (row == r31);
            a0 = last ? c0 : 0.f;
            a1 = last ? c1 : 0.f;
            a2 = last ? c2 : 0.f;
            a3 = last ? c3 : 0.f;
            cur_row = r31;
        }
    }
    flush_row(cur_row, a0, a1, a2, a3, lane, out);
}

extern "C" void kernel_launch(void* const* d_in, const int* in_sizes, int n_in,
                              void* d_out, int out_size) {
    const float*    x    = (const float*)d_in[0];
    const float*    vals = (const float*)d_in[1];
    const unsigned* rows = (const unsigned*)d_in[2];
    const unsigned* cols = (const unsigned*)d_in[3];
    float*          out  = (float*)d_out;

    k_prep<<<131072 / 256, 256>>>((const float4*)x, rows, (float4*)out);
    k_spmm<<<TOTAL_WARPS * 32 / 256, 256>>>(vals, rows, cols, out);
}